// round 1
// baseline (speedup 1.0000x reference)
#include <cuda_runtime.h>
#include <math.h>

// Problem constants
#define NROWS 16384
#define FIN   512
#define FHID  256

// Scratch (allocation-free rule: __device__ globals)
__device__ float g_support[(size_t)NROWS * FHID];   // 16 MiB
__device__ float g_embed_fallback[(size_t)NROWS * FHID]; // in case out_size lacks embed1

// ---------------- SGEMM: C[M,256] = A[M,K] @ B[K,256] (+ bias) ----------------
// BM=64, BN=256 (== N, so A is streamed exactly once), BK=16, 8x8 microtile,
// 256 threads. Split-N register tiles for conflict-free LDS.128 on Bs.
#define BM 64
#define BN 256
#define BK 16
#define TM 8
#define TN 8
#define APAD 4   // As row pad to soften transpose-store conflicts

__global__ __launch_bounds__(256, 2)
void sgemm_n256_bias(const float* __restrict__ A,
                     const float* __restrict__ B,
                     const float* __restrict__ bias,   // may be nullptr
                     float* __restrict__ C,
                     int M, int Kdim)
{
    __shared__ float As[BK][BM + APAD];
    __shared__ float Bs[BK][BN];

    const int tid      = threadIdx.x;
    const int blockRow = blockIdx.x;          // M / BM blocks; N fits in one BN
    const int tRow     = tid >> 5;            // 0..7   (warp id)
    const int tCol     = tid & 31;            // 0..31  (lane)

    const float* Ab = A + (size_t)blockRow * BM * Kdim;

    float acc[TM][TN];
    #pragma unroll
    for (int i = 0; i < TM; i++)
        #pragma unroll
        for (int j = 0; j < TN; j++) acc[i][j] = 0.0f;

    // A tile load mapping: 64 rows x 16 cols = 256 float4, 1 per thread
    const int aRow  = tid >> 2;               // 0..63
    const int aCol4 = (tid & 3) * 4;          // 0,4,8,12
    // B tile load mapping: 16 rows x 256 cols = 1024 float4, 4 per thread
    const int bRow  = tid >> 6;               // 0..3  (+4 per pass)
    const int bCol4 = (tid & 63) * 4;         // 0..252

    for (int k0 = 0; k0 < Kdim; k0 += BK) {
        // ---- load A tile (transposed into As[k][m]) ----
        float4 av = *reinterpret_cast<const float4*>(
            Ab + (size_t)aRow * Kdim + (k0 + aCol4));
        As[aCol4 + 0][aRow] = av.x;
        As[aCol4 + 1][aRow] = av.y;
        As[aCol4 + 2][aRow] = av.z;
        As[aCol4 + 3][aRow] = av.w;

        // ---- load B tile (row-major, N == BN == 256) ----
        #pragma unroll
        for (int p = 0; p < 4; p++) {
            int r = bRow + p * 4;
            *reinterpret_cast<float4*>(&Bs[r][bCol4]) =
                *reinterpret_cast<const float4*>(B + (size_t)(k0 + r) * BN + bCol4);
        }
        __syncthreads();

        // ---- compute ----
        #pragma unroll
        for (int k = 0; k < BK; k++) {
            float ra[TM], rb[TN];
            #pragma unroll
            for (int i = 0; i < TM; i++) ra[i] = As[k][tRow * TM + i]; // broadcast
            // split-N: cols [tCol*4 .. +4) and [128 + tCol*4 .. +4) — conflict-free
            float4 b0 = *reinterpret_cast<const float4*>(&Bs[k][tCol * 4]);
            float4 b1 = *reinterpret_cast<const float4*>(&Bs[k][128 + tCol * 4]);
            rb[0] = b0.x; rb[1] = b0.y; rb[2] = b0.z; rb[3] = b0.w;
            rb[4] = b1.x; rb[5] = b1.y; rb[6] = b1.z; rb[7] = b1.w;
            #pragma unroll
            for (int i = 0; i < TM; i++)
                #pragma unroll
                for (int j = 0; j < TN; j++)
                    acc[i][j] = fmaf(ra[i], rb[j], acc[i][j]);
        }
        __syncthreads();
    }

    // ---- epilogue: optional bias, split-N stores ----
    float4 bv0 = make_float4(0.f, 0.f, 0.f, 0.f);
    float4 bv1 = make_float4(0.f, 0.f, 0.f, 0.f);
    if (bias) {
        bv0 = *reinterpret_cast<const float4*>(bias + tCol * 4);
        bv1 = *reinterpret_cast<const float4*>(bias + 128 + tCol * 4);
    }
    #pragma unroll
    for (int i = 0; i < TM; i++) {
        int gr = blockRow * BM + tRow * TM + i;
        float* Crow = C + (size_t)gr * BN;
        float4 v0, v1;
        v0.x = acc[i][0] + bv0.x; v0.y = acc[i][1] + bv0.y;
        v0.z = acc[i][2] + bv0.z; v0.w = acc[i][3] + bv0.w;
        v1.x = acc[i][4] + bv1.x; v1.y = acc[i][5] + bv1.y;
        v1.z = acc[i][6] + bv1.z; v1.w = acc[i][7] + bv1.w;
        *reinterpret_cast<float4*>(Crow + tCol * 4)       = v0;
        *reinterpret_cast<float4*>(Crow + 128 + tCol * 4) = v1;
    }
}

// ---------------- row-wise log_softmax over FHID=256 ----------------
__global__ __launch_bounds__(256)
void row_logsoftmax(const float* __restrict__ E, float* __restrict__ P)
{
    const int row = blockIdx.x;
    const int t   = threadIdx.x;
    const float v = E[(size_t)row * FHID + t];

    __shared__ float smax[8];
    __shared__ float ssum[8];

    float m = v;
    #pragma unroll
    for (int o = 16; o > 0; o >>= 1)
        m = fmaxf(m, __shfl_xor_sync(0xffffffffu, m, o));
    if ((t & 31) == 0) smax[t >> 5] = m;
    __syncthreads();
    float mm = smax[0];
    #pragma unroll
    for (int w = 1; w < 8; w++) mm = fmaxf(mm, smax[w]);

    float ex = expf(v - mm);
    float s = ex;
    #pragma unroll
    for (int o = 16; o > 0; o >>= 1)
        s += __shfl_xor_sync(0xffffffffu, s, o);
    if ((t & 31) == 0) ssum[t >> 5] = s;
    __syncthreads();
    float tot = 0.0f;
    #pragma unroll
    for (int w = 0; w < 8; w++) tot += ssum[w];

    const float lse = mm + logf(tot);
    P[(size_t)row * FHID + t] = v - lse;
}

// ---------------- launch ----------------
extern "C" void kernel_launch(void* const* d_in, const int* in_sizes, int n_in,
                              void* d_out, int out_size)
{
    const float* x   = (const float*)d_in[0];   // [16384, 512]
    const float* adj = (const float*)d_in[1];   // [16384, 16384]
    const float* W   = (const float*)d_in[2];   // [512, 256]
    const float* b   = (const float*)d_in[3];   // [256]
    float* out = (float*)d_out;

    float* support;
    cudaGetSymbolAddress((void**)&support, g_support);

    // Output layout: [logp (16384*256), embed1 (16384*256)] concatenated.
    float* logp  = out;
    float* embed;
    if (out_size >= 2 * NROWS * FHID) {
        embed = out + (size_t)NROWS * FHID;
    } else {
        cudaGetSymbolAddress((void**)&embed, g_embed_fallback);
    }

    // 1) support = x @ W              (M=16384, K=512)
    sgemm_n256_bias<<<NROWS / BM, 256>>>(x, W, nullptr, support, NROWS, FIN);

    // 2) embed = adj @ support + b    (M=16384, K=16384)  -- dominant
    sgemm_n256_bias<<<NROWS / BM, 256>>>(adj, support, b, embed, NROWS, NROWS);

    // 3) logp = log_softmax(embed, dim=1)
    row_logsoftmax<<<NROWS, 256>>>(embed, logp);
}

// round 3
// speedup vs baseline: 2.5128x; 2.5128x over previous
#include <cuda_runtime.h>
#include <cuda_fp16.h>
#include <math.h>
#include <stdint.h>

#define NROWS 16384
#define FIN   512
#define FHID  256

// ---------------- scratch (__device__ globals; no allocation) ----------------
__device__ float  g_support[(size_t)NROWS * FHID];        // 16 MiB fp32
__device__ __half g_sT_hi[(size_t)FHID * NROWS];          // 8 MiB  supportT hi
__device__ __half g_sT_lo[(size_t)FHID * NROWS];          // 8 MiB  supportT lo
__device__ float  g_embed_fallback[(size_t)NROWS * FHID];

// ---------------- small asm helpers (all arch-neutral PTX, sm_80+) ----------------
__device__ __forceinline__ uint32_t smem_u32(const void* p) {
    uint32_t a;
    asm("{ .reg .u64 t; cvta.to.shared.u64 t, %1; cvt.u32.u64 %0, t; }" : "=r"(a) : "l"(p));
    return a;
}
#define CP_ASYNC16(dst, src) \
    asm volatile("cp.async.cg.shared.global [%0], [%1], 16;" :: "r"(dst), "l"(src))
#define CP_COMMIT() asm volatile("cp.async.commit_group;" ::: "memory")
#define CP_WAIT1()  asm volatile("cp.async.wait_group 1;" ::: "memory")
#define CP_WAIT0()  asm volatile("cp.async.wait_group 0;" ::: "memory")
#define LDSM4(r, a) \
    asm volatile("ldmatrix.sync.aligned.m8n8.x4.shared.b16 {%0,%1,%2,%3}, [%4];" \
        : "=r"((r)[0]), "=r"((r)[1]), "=r"((r)[2]), "=r"((r)[3]) : "r"(a))
#define MMA16816(c, a, b) \
    asm volatile("mma.sync.aligned.m16n8k16.row.col.f32.f16.f16.f32 " \
        "{%0,%1,%2,%3}, {%4,%5,%6,%7}, {%8,%9}, {%0,%1,%2,%3};" \
        : "+f"((c)[0]), "+f"((c)[1]), "+f"((c)[2]), "+f"((c)[3]) \
        : "r"((a)[0]), "r"((a)[1]), "r"((a)[2]), "r"((a)[3]), "r"((b)[0]), "r"((b)[1]))

// ================= GEMM1: support = x @ W (fp32 FFMA, proven 111us) =================
#define BM 64
#define BN 256
#define BK 16
#define TM 8
#define TN 8
#define APAD 4

__global__ __launch_bounds__(256, 2)
void sgemm_n256(const float* __restrict__ A, const float* __restrict__ B,
                float* __restrict__ C, int Kdim)
{
    __shared__ float As[BK][BM + APAD];
    __shared__ float Bs[BK][BN];
    const int tid = threadIdx.x, blockRow = blockIdx.x;
    const int tRow = tid >> 5, tCol = tid & 31;
    const float* Ab = A + (size_t)blockRow * BM * Kdim;
    float acc[TM][TN];
    #pragma unroll
    for (int i = 0; i < TM; i++)
        #pragma unroll
        for (int j = 0; j < TN; j++) acc[i][j] = 0.0f;
    const int aRow = tid >> 2, aCol4 = (tid & 3) * 4;
    const int bRow = tid >> 6, bCol4 = (tid & 63) * 4;
    for (int k0 = 0; k0 < Kdim; k0 += BK) {
        float4 av = *reinterpret_cast<const float4*>(Ab + (size_t)aRow * Kdim + (k0 + aCol4));
        As[aCol4 + 0][aRow] = av.x; As[aCol4 + 1][aRow] = av.y;
        As[aCol4 + 2][aRow] = av.z; As[aCol4 + 3][aRow] = av.w;
        #pragma unroll
        for (int p = 0; p < 4; p++) {
            int r = bRow + p * 4;
            *reinterpret_cast<float4*>(&Bs[r][bCol4]) =
                *reinterpret_cast<const float4*>(B + (size_t)(k0 + r) * BN + bCol4);
        }
        __syncthreads();
        #pragma unroll
        for (int k = 0; k < BK; k++) {
            float ra[TM], rb[TN];
            #pragma unroll
            for (int i = 0; i < TM; i++) ra[i] = As[k][tRow * TM + i];
            float4 b0 = *reinterpret_cast<const float4*>(&Bs[k][tCol * 4]);
            float4 b1 = *reinterpret_cast<const float4*>(&Bs[k][128 + tCol * 4]);
            rb[0]=b0.x; rb[1]=b0.y; rb[2]=b0.z; rb[3]=b0.w;
            rb[4]=b1.x; rb[5]=b1.y; rb[6]=b1.z; rb[7]=b1.w;
            #pragma unroll
            for (int i = 0; i < TM; i++)
                #pragma unroll
                for (int j = 0; j < TN; j++) acc[i][j] = fmaf(ra[i], rb[j], acc[i][j]);
        }
        __syncthreads();
    }
    #pragma unroll
    for (int i = 0; i < TM; i++) {
        int gr = blockRow * BM + tRow * TM + i;
        float* Crow = C + (size_t)gr * BN;
        *reinterpret_cast<float4*>(Crow + tCol * 4) =
            make_float4(acc[i][0], acc[i][1], acc[i][2], acc[i][3]);
        *reinterpret_cast<float4*>(Crow + 128 + tCol * 4) =
            make_float4(acc[i][4], acc[i][5], acc[i][6], acc[i][7]);
    }
}

// ====== transpose + fp16 split: sT[h][n] = hi/lo(support[n][h]) ======
__global__ __launch_bounds__(256)
void transpose_split(const float* __restrict__ S,
                     __half* __restrict__ Th, __half* __restrict__ Tl)
{
    __shared__ float ts[32][33];
    const int n0 = blockIdx.x * 32, h0 = blockIdx.y * 32;
    const int tx = threadIdx.x & 31, ty = threadIdx.x >> 5;  // 32 x 8
    #pragma unroll
    for (int k = 0; k < 4; k++)
        ts[ty + 8 * k][tx] = S[(size_t)(n0 + ty + 8 * k) * FHID + h0 + tx];
    __syncthreads();
    #pragma unroll
    for (int k = 0; k < 4; k++) {
        int h = h0 + ty + 8 * k, n = n0 + tx;
        float v = ts[tx][ty + 8 * k];
        __half hb = __float2half_rn(v);
        float hf = __half2float(hb);
        __half lb = __float2half_rn(v - hf);
        Th[(size_t)h * NROWS + n] = hb;
        Tl[(size_t)h * NROWS + n] = lb;
    }
}

// ============ GEMM2: embed = adj @ support + b  (HMMA fp16 3-split) ============
// BM2=128, BN2=256(=FHID: adj read once), BK2=32, 512 threads = 16 warps (4Mx4N),
// warptile 32x64. Double-buffered smem, cp.async for B(hi/lo), A converted in regs.
#define BM2 128
#define BK2 32
#define LDS2 40                    // halves per smem row (8-half pad: conflict-free ldsm)
#define SA_HI 0
#define SA_LO 10240                // 128*40*2
#define SB_HI 20480
#define SB_LO 40960                // + 256*40*2
#define STG2  61440
#define NCH2  (NROWS / BK2)        // 512 chunks

__global__ __launch_bounds__(512, 1)
void gemm2_hmma(const float* __restrict__ adj,
                const __half* __restrict__ Bh, const __half* __restrict__ Bl,
                const float* __restrict__ bias,
                float* __restrict__ embed)
{
    extern __shared__ char sm[];
    const uint32_t sb = smem_u32(sm);
    const int tid  = threadIdx.x;
    const int lane = tid & 31, wid = tid >> 5;
    const int wm = wid >> 2, wn = wid & 3;       // 4 x 4 warp grid
    const int mblk = blockIdx.x * BM2;

    float acc[2][8][4];
    #pragma unroll
    for (int i = 0; i < 2; i++)
        #pragma unroll
        for (int j = 0; j < 8; j++)
            #pragma unroll
            for (int q = 0; q < 4; q++) acc[i][j][q] = 0.0f;

    // ---- cp.async B tiles: 256 rows x 32 halves, hi+lo; 2+2 16B ops/thread ----
    auto issueB = [&](int c, int s) {
        const size_t k0 = (size_t)c * BK2;
        #pragma unroll
        for (int i = 0; i < 2; i++) {
            int o = tid + i * 512;
            int row = o >> 2, kc = o & 3;
            const __half* srch = Bh + (size_t)row * NROWS + k0 + kc * 8;
            const __half* srcl = Bl + (size_t)row * NROWS + k0 + kc * 8;
            uint32_t off = (uint32_t)(row * LDS2 + kc * 8) * 2;
            CP_ASYNC16(sb + s * STG2 + SB_HI + off, srch);
            CP_ASYNC16(sb + s * STG2 + SB_LO + off, srcl);
        }
    };
    // ---- A: 128 rows x 32 fp32; 2 float4/thread ----
    auto ldgA = [&](int c, float4 av[2]) {
        #pragma unroll
        for (int i = 0; i < 2; i++) {
            int o = tid + i * 512;
            int row = o >> 3, c4 = o & 7;
            av[i] = *reinterpret_cast<const float4*>(
                adj + (size_t)(mblk + row) * NROWS + (size_t)c * BK2 + c4 * 4);
        }
    };
    auto storeA = [&](const float4 av[2], int s) {
        #pragma unroll
        for (int i = 0; i < 2; i++) {
            int o = tid + i * 512;
            int row = o >> 3, c4 = o & 7;
            float4 v = av[i];
            __half2 h0 = __float22half2_rn(make_float2(v.x, v.y));
            __half2 h1 = __float22half2_rn(make_float2(v.z, v.w));
            float2 f0 = __half22float2(h0), f1 = __half22float2(h1);
            __half2 l0 = __float22half2_rn(make_float2(v.x - f0.x, v.y - f0.y));
            __half2 l1 = __float22half2_rn(make_float2(v.z - f1.x, v.w - f1.y));
            uint32_t off = (uint32_t)(row * LDS2 + c4 * 4) * 2;
            *reinterpret_cast<uint2*>(sm + s * STG2 + SA_HI + off) =
                make_uint2(*reinterpret_cast<uint32_t*>(&h0), *reinterpret_cast<uint32_t*>(&h1));
            *reinterpret_cast<uint2*>(sm + s * STG2 + SA_LO + off) =
                make_uint2(*reinterpret_cast<uint32_t*>(&l0), *reinterpret_cast<uint32_t*>(&l1));
        }
    };
    auto compute = [&](int s) {
        const uint32_t base = sb + s * STG2;
        #pragma unroll
        for (int kk = 0; kk < 2; kk++) {
            uint32_t ah[2][4], al[2][4];
            const int arow = lane & 15;
            const int acol = kk * 16 + (lane >> 4) * 8;
            #pragma unroll
            for (int mi = 0; mi < 2; mi++) {
                uint32_t ao = (uint32_t)((wm * 32 + mi * 16 + arow) * LDS2 + acol) * 2;
                LDSM4(ah[mi], base + SA_HI + ao);
                LDSM4(al[mi], base + SA_LO + ao);
            }
            #pragma unroll
            for (int g = 0; g < 4; g++) {
                const int nrow = wn * 64 + g * 16 + (lane & 7) + ((lane >> 4) << 3);
                const int ncol = kk * 16 + ((lane >> 3) & 1) * 8;
                uint32_t bo = (uint32_t)(nrow * LDS2 + ncol) * 2;
                uint32_t bh[4], bl[4];
                LDSM4(bh, base + SB_HI + bo);
                LDSM4(bl, base + SB_LO + bo);
                #pragma unroll
                for (int mi = 0; mi < 2; mi++)
                    #pragma unroll
                    for (int q = 0; q < 2; q++) {
                        float* c = acc[mi][g * 2 + q];
                        MMA16816(c, ah[mi], &bh[2 * q]);   // hi*hi
                        MMA16816(c, al[mi], &bh[2 * q]);   // lo*hi
                        MMA16816(c, ah[mi], &bl[2 * q]);   // hi*lo
                    }
            }
        }
    };

    // ---- prologue ----
    float4 av[2];
    issueB(0, 0); CP_COMMIT();
    ldgA(0, av);  storeA(av, 0);
    issueB(1, 1); CP_COMMIT();

    // ---- mainloop ----
    for (int c = 0; c < NCH2; ++c) {
        const bool more = (c + 1 < NCH2);
        if (more) ldgA(c + 1, av);
        if (more) CP_WAIT1(); else CP_WAIT0();
        __syncthreads();
        compute(c & 1);
        if (more) storeA(av, (c + 1) & 1);
        __syncthreads();
        if (c + 2 < NCH2) { issueB(c + 2, c & 1); CP_COMMIT(); }
    }

    // ---- epilogue: + bias, store embed ----
    #pragma unroll
    for (int ni = 0; ni < 8; ni++) {
        const int col = wn * 64 + ni * 8 + (lane & 3) * 2;
        const float2 bv = *reinterpret_cast<const float2*>(bias + col);
        #pragma unroll
        for (int mi = 0; mi < 2; mi++) {
            const int r0 = mblk + wm * 32 + mi * 16 + (lane >> 2);
            const float* c = acc[mi][ni];
            *reinterpret_cast<float2*>(embed + (size_t)r0 * FHID + col) =
                make_float2(c[0] + bv.x, c[1] + bv.y);
            *reinterpret_cast<float2*>(embed + (size_t)(r0 + 8) * FHID + col) =
                make_float2(c[2] + bv.x, c[3] + bv.y);
        }
    }
}

// ---------------- row-wise log_softmax over FHID=256 ----------------
__global__ __launch_bounds__(256)
void row_logsoftmax(const float* __restrict__ E, float* __restrict__ P)
{
    const int row = blockIdx.x;
    const int t   = threadIdx.x;
    const float v = E[(size_t)row * FHID + t];
    __shared__ float smax[8];
    __shared__ float ssum[8];
    float m = v;
    #pragma unroll
    for (int o = 16; o > 0; o >>= 1)
        m = fmaxf(m, __shfl_xor_sync(0xffffffffu, m, o));
    if ((t & 31) == 0) smax[t >> 5] = m;
    __syncthreads();
    float mm = smax[0];
    #pragma unroll
    for (int w = 1; w < 8; w++) mm = fmaxf(mm, smax[w]);
    float ex = expf(v - mm);
    float s = ex;
    #pragma unroll
    for (int o = 16; o > 0; o >>= 1)
        s += __shfl_xor_sync(0xffffffffu, s, o);
    if ((t & 31) == 0) ssum[t >> 5] = s;
    __syncthreads();
    float tot = 0.0f;
    #pragma unroll
    for (int w = 0; w < 8; w++) tot += ssum[w];
    const float lse = mm + logf(tot);
    P[(size_t)row * FHID + t] = v - lse;
}

// ================= launch =================
extern "C" void kernel_launch(void* const* d_in, const int* in_sizes, int n_in,
                              void* d_out, int out_size)
{
    const float* x   = (const float*)d_in[0];
    const float* adj = (const float*)d_in[1];
    const float* W   = (const float*)d_in[2];
    const float* b   = (const float*)d_in[3];
    float* out = (float*)d_out;

    float *support, *embed;
    __half *sTh, *sTl;
    cudaGetSymbolAddress((void**)&support, g_support);
    cudaGetSymbolAddress((void**)&sTh, g_sT_hi);
    cudaGetSymbolAddress((void**)&sTl, g_sT_lo);

    float* logp = out;
    if (out_size >= 2 * NROWS * FHID) embed = out + (size_t)NROWS * FHID;
    else cudaGetSymbolAddress((void**)&embed, g_embed_fallback);

    cudaFuncSetAttribute(gemm2_hmma, cudaFuncAttributeMaxDynamicSharedMemorySize, 2 * STG2);

    // 1) support = x @ W (fp32)
    sgemm_n256<<<NROWS / BM, 256>>>(x, W, support, FIN);
    // 2) supportT -> fp16 hi/lo, [FHID][NROWS]
    transpose_split<<<dim3(NROWS / 32, FHID / 32), 256>>>(support, sTh, sTl);
    // 3) embed = adj @ support + b  (HMMA 3-split)
    gemm2_hmma<<<NROWS / BM2, 512, 2 * STG2>>>(adj, sTh, sTl, b, embed);
    // 4) logp = log_softmax(embed)
    row_logsoftmax<<<NROWS, 256>>>(embed, logp);
}

// round 4
// speedup vs baseline: 3.4929x; 1.3900x over previous
#include <cuda_runtime.h>
#include <cuda_fp16.h>
#include <math.h>
#include <stdint.h>

#define NROWS 16384
#define FIN   512
#define FHID  256

// ---------------- scratch (__device__ globals; no allocation) ----------------
__device__ float  g_support[(size_t)NROWS * FHID];        // 16 MiB fp32
__device__ __half g_sT_hi[(size_t)FHID * NROWS];          // 8 MiB  supportT (fp16)
__device__ float  g_embed_fallback[(size_t)NROWS * FHID];

// ---------------- asm helpers (arch-neutral PTX, sm_80+) ----------------
__device__ __forceinline__ uint32_t smem_u32(const void* p) {
    uint32_t a;
    asm("{ .reg .u64 t; cvta.to.shared.u64 t, %1; cvt.u32.u64 %0, t; }" : "=r"(a) : "l"(p));
    return a;
}
#define CP_ASYNC16(dst, src) \
    asm volatile("cp.async.cg.shared.global [%0], [%1], 16;" :: "r"(dst), "l"(src))
#define CP_COMMIT() asm volatile("cp.async.commit_group;" ::: "memory")
#define CP_WAIT1()  asm volatile("cp.async.wait_group 1;" ::: "memory")
#define CP_WAIT0()  asm volatile("cp.async.wait_group 0;" ::: "memory")
#define LDSM4(r, a) \
    asm volatile("ldmatrix.sync.aligned.m8n8.x4.shared.b16 {%0,%1,%2,%3}, [%4];" \
        : "=r"((r)[0]), "=r"((r)[1]), "=r"((r)[2]), "=r"((r)[3]) : "r"(a))
#define MMA16816(c, a, b) \
    asm volatile("mma.sync.aligned.m16n8k16.row.col.f32.f16.f16.f32 " \
        "{%0,%1,%2,%3}, {%4,%5,%6,%7}, {%8,%9}, {%0,%1,%2,%3};" \
        : "+f"((c)[0]), "+f"((c)[1]), "+f"((c)[2]), "+f"((c)[3]) \
        : "r"((a)[0]), "r"((a)[1]), "r"((a)[2]), "r"((a)[3]), "r"((b)[0]), "r"((b)[1]))

// ================= GEMM1: support = x @ W (fp32 FFMA, proven) =================
#define BM 64
#define BN 256
#define BK 16
#define TM 8
#define TN 8
#define APAD 4

__global__ __launch_bounds__(256, 2)
void sgemm_n256(const float* __restrict__ A, const float* __restrict__ B,
                float* __restrict__ C, int Kdim)
{
    __shared__ float As[BK][BM + APAD];
    __shared__ float Bs[BK][BN];
    const int tid = threadIdx.x, blockRow = blockIdx.x;
    const int tRow = tid >> 5, tCol = tid & 31;
    const float* Ab = A + (size_t)blockRow * BM * Kdim;
    float acc[TM][TN];
    #pragma unroll
    for (int i = 0; i < TM; i++)
        #pragma unroll
        for (int j = 0; j < TN; j++) acc[i][j] = 0.0f;
    const int aRow = tid >> 2, aCol4 = (tid & 3) * 4;
    const int bRow = tid >> 6, bCol4 = (tid & 63) * 4;
    for (int k0 = 0; k0 < Kdim; k0 += BK) {
        float4 av = *reinterpret_cast<const float4*>(Ab + (size_t)aRow * Kdim + (k0 + aCol4));
        As[aCol4 + 0][aRow] = av.x; As[aCol4 + 1][aRow] = av.y;
        As[aCol4 + 2][aRow] = av.z; As[aCol4 + 3][aRow] = av.w;
        #pragma unroll
        for (int p = 0; p < 4; p++) {
            int r = bRow + p * 4;
            *reinterpret_cast<float4*>(&Bs[r][bCol4]) =
                *reinterpret_cast<const float4*>(B + (size_t)(k0 + r) * BN + bCol4);
        }
        __syncthreads();
        #pragma unroll
        for (int k = 0; k < BK; k++) {
            float ra[TM], rb[TN];
            #pragma unroll
            for (int i = 0; i < TM; i++) ra[i] = As[k][tRow * TM + i];
            float4 b0 = *reinterpret_cast<const float4*>(&Bs[k][tCol * 4]);
            float4 b1 = *reinterpret_cast<const float4*>(&Bs[k][128 + tCol * 4]);
            rb[0]=b0.x; rb[1]=b0.y; rb[2]=b0.z; rb[3]=b0.w;
            rb[4]=b1.x; rb[5]=b1.y; rb[6]=b1.z; rb[7]=b1.w;
            #pragma unroll
            for (int i = 0; i < TM; i++)
                #pragma unroll
                for (int j = 0; j < TN; j++) acc[i][j] = fmaf(ra[i], rb[j], acc[i][j]);
        }
        __syncthreads();
    }
    #pragma unroll
    for (int i = 0; i < TM; i++) {
        int gr = blockRow * BM + tRow * TM + i;
        float* Crow = C + (size_t)gr * BN;
        *reinterpret_cast<float4*>(Crow + tCol * 4) =
            make_float4(acc[i][0], acc[i][1], acc[i][2], acc[i][3]);
        *reinterpret_cast<float4*>(Crow + 128 + tCol * 4) =
            make_float4(acc[i][4], acc[i][5], acc[i][6], acc[i][7]);
    }
}

// ====== transpose + fp16 round: sT[h][n] = fp16(support[n][h]) ======
__global__ __launch_bounds__(256)
void transpose_half(const float* __restrict__ S, __half* __restrict__ Th)
{
    __shared__ float ts[32][33];
    const int n0 = blockIdx.x * 32, h0 = blockIdx.y * 32;
    const int tx = threadIdx.x & 31, ty = threadIdx.x >> 5;  // 32 x 8
    #pragma unroll
    for (int k = 0; k < 4; k++)
        ts[ty + 8 * k][tx] = S[(size_t)(n0 + ty + 8 * k) * FHID + h0 + tx];
    __syncthreads();
    #pragma unroll
    for (int k = 0; k < 4; k++) {
        int h = h0 + ty + 8 * k, n = n0 + tx;
        Th[(size_t)h * NROWS + n] = __float2half_rn(ts[tx][ty + 8 * k]);
    }
}

// ============ GEMM2: embed = adj @ support + b  (HMMA, 2-term split on A) ============
// BM2=64, BN=256(=FHID: adj streamed once), BK2=32, 256 threads = 8 warps (2Mx4N),
// warptile 32x64. Double-buffered smem; B(hi) via cp.async; A converted in regs
// to fp16 hi+lo (C ~= ah*bh + al*bh; B's fp16 rounding error is the accepted term).
#define BM2 64
#define BK2 32
#define LDS2 40                    // halves per smem row (8-half pad)
#define SA_HI 0
#define SA_LO 5120                 // 64*40*2
#define SB_HI 10240
#define STG2  30720                // + 256*40*2
#define NCH2  (NROWS / BK2)        // 512 chunks

__global__ __launch_bounds__(256, 2)
void gemm2_hmma(const float* __restrict__ adj,
                const __half* __restrict__ Bh,
                const float* __restrict__ bias,
                float* __restrict__ embed)
{
    extern __shared__ char sm[];
    const uint32_t sb = smem_u32(sm);
    const int tid  = threadIdx.x;
    const int lane = tid & 31, wid = tid >> 5;
    const int wm = wid >> 2, wn = wid & 3;       // 2 x 4 warp grid
    const int mblk = blockIdx.x * BM2;

    float acc[2][8][4];
    #pragma unroll
    for (int i = 0; i < 2; i++)
        #pragma unroll
        for (int j = 0; j < 8; j++)
            #pragma unroll
            for (int q = 0; q < 4; q++) acc[i][j][q] = 0.0f;

    // ---- cp.async B tile: 256 rows x 32 halves (hi only); 4 x 16B per thread ----
    auto issueB = [&](int c, int s) {
        const size_t k0 = (size_t)c * BK2;
        #pragma unroll
        for (int i = 0; i < 4; i++) {
            int o = tid + i * 256;
            int row = o >> 2, kc = o & 3;
            const __half* src = Bh + (size_t)row * NROWS + k0 + kc * 8;
            uint32_t off = (uint32_t)(row * LDS2 + kc * 8) * 2;
            CP_ASYNC16(sb + s * STG2 + SB_HI + off, src);
        }
    };
    // ---- A: 64 rows x 32 fp32; 2 float4 per thread ----
    auto ldgA = [&](int c, float4 av[2]) {
        #pragma unroll
        for (int i = 0; i < 2; i++) {
            int o = tid + i * 256;
            int row = o >> 3, c4 = o & 7;
            av[i] = *reinterpret_cast<const float4*>(
                adj + (size_t)(mblk + row) * NROWS + (size_t)c * BK2 + c4 * 4);
        }
    };
    auto storeA = [&](const float4 av[2], int s) {
        #pragma unroll
        for (int i = 0; i < 2; i++) {
            int o = tid + i * 256;
            int row = o >> 3, c4 = o & 7;
            float4 v = av[i];
            __half2 h0 = __float22half2_rn(make_float2(v.x, v.y));
            __half2 h1 = __float22half2_rn(make_float2(v.z, v.w));
            float2 f0 = __half22float2(h0), f1 = __half22float2(h1);
            __half2 l0 = __float22half2_rn(make_float2(v.x - f0.x, v.y - f0.y));
            __half2 l1 = __float22half2_rn(make_float2(v.z - f1.x, v.w - f1.y));
            uint32_t off = (uint32_t)(row * LDS2 + c4 * 4) * 2;
            *reinterpret_cast<uint2*>(sm + s * STG2 + SA_HI + off) =
                make_uint2(*reinterpret_cast<uint32_t*>(&h0), *reinterpret_cast<uint32_t*>(&h1));
            *reinterpret_cast<uint2*>(sm + s * STG2 + SA_LO + off) =
                make_uint2(*reinterpret_cast<uint32_t*>(&l0), *reinterpret_cast<uint32_t*>(&l1));
        }
    };
    auto compute = [&](int s) {
        const uint32_t base = sb + s * STG2;
        #pragma unroll
        for (int kk = 0; kk < 2; kk++) {
            uint32_t ah[2][4], al[2][4];
            const int arow = lane & 15;
            const int acol = kk * 16 + (lane >> 4) * 8;
            #pragma unroll
            for (int mi = 0; mi < 2; mi++) {
                uint32_t ao = (uint32_t)((wm * 32 + mi * 16 + arow) * LDS2 + acol) * 2;
                LDSM4(ah[mi], base + SA_HI + ao);
                LDSM4(al[mi], base + SA_LO + ao);
            }
            #pragma unroll
            for (int g = 0; g < 4; g++) {
                const int nrow = wn * 64 + g * 16 + (lane & 7) + ((lane >> 4) << 3);
                const int ncol = kk * 16 + ((lane >> 3) & 1) * 8;
                uint32_t bo = (uint32_t)(nrow * LDS2 + ncol) * 2;
                uint32_t bh[4];
                LDSM4(bh, base + SB_HI + bo);
                #pragma unroll
                for (int mi = 0; mi < 2; mi++)
                    #pragma unroll
                    for (int q = 0; q < 2; q++) {
                        float* c = acc[mi][g * 2 + q];
                        MMA16816(c, ah[mi], &bh[2 * q]);   // hi * b
                        MMA16816(c, al[mi], &bh[2 * q]);   // lo * b
                    }
            }
        }
    };

    // ---- prologue ----
    float4 av[2];
    issueB(0, 0); CP_COMMIT();
    ldgA(0, av);  storeA(av, 0);
    issueB(1, 1); CP_COMMIT();

    // ---- mainloop ----
    for (int c = 0; c < NCH2; ++c) {
        const bool more = (c + 1 < NCH2);
        if (more) ldgA(c + 1, av);
        if (more) CP_WAIT1(); else CP_WAIT0();
        __syncthreads();
        compute(c & 1);
        if (more) storeA(av, (c + 1) & 1);
        __syncthreads();
        if (c + 2 < NCH2) { issueB(c + 2, c & 1); CP_COMMIT(); }
    }

    // ---- epilogue: + bias, store embed ----
    #pragma unroll
    for (int ni = 0; ni < 8; ni++) {
        const int col = wn * 64 + ni * 8 + (lane & 3) * 2;
        const float2 bv = *reinterpret_cast<const float2*>(bias + col);
        #pragma unroll
        for (int mi = 0; mi < 2; mi++) {
            const int r0 = mblk + wm * 32 + mi * 16 + (lane >> 2);
            const float* c = acc[mi][ni];
            *reinterpret_cast<float2*>(embed + (size_t)r0 * FHID + col) =
                make_float2(c[0] + bv.x, c[1] + bv.y);
            *reinterpret_cast<float2*>(embed + (size_t)(r0 + 8) * FHID + col) =
                make_float2(c[2] + bv.x, c[3] + bv.y);
        }
    }
}

// ---------------- row-wise log_softmax over FHID=256 ----------------
__global__ __launch_bounds__(256)
void row_logsoftmax(const float* __restrict__ E, float* __restrict__ P)
{
    const int row = blockIdx.x;
    const int t   = threadIdx.x;
    const float v = E[(size_t)row * FHID + t];
    __shared__ float smax[8];
    __shared__ float ssum[8];
    float m = v;
    #pragma unroll
    for (int o = 16; o > 0; o >>= 1)
        m = fmaxf(m, __shfl_xor_sync(0xffffffffu, m, o));
    if ((t & 31) == 0) smax[t >> 5] = m;
    __syncthreads();
    float mm = smax[0];
    #pragma unroll
    for (int w = 1; w < 8; w++) mm = fmaxf(mm, smax[w]);
    float ex = expf(v - mm);
    float s = ex;
    #pragma unroll
    for (int o = 16; o > 0; o >>= 1)
        s += __shfl_xor_sync(0xffffffffu, s, o);
    if ((t & 31) == 0) ssum[t >> 5] = s;
    __syncthreads();
    float tot = 0.0f;
    #pragma unroll
    for (int w = 0; w < 8; w++) tot += ssum[w];
    const float lse = mm + logf(tot);
    P[(size_t)row * FHID + t] = v - lse;
}

// ================= launch =================
extern "C" void kernel_launch(void* const* d_in, const int* in_sizes, int n_in,
                              void* d_out, int out_size)
{
    const float* x   = (const float*)d_in[0];
    const float* adj = (const float*)d_in[1];
    const float* W   = (const float*)d_in[2];
    const float* b   = (const float*)d_in[3];
    float* out = (float*)d_out;

    float *support, *embed;
    __half *sTh;
    cudaGetSymbolAddress((void**)&support, g_support);
    cudaGetSymbolAddress((void**)&sTh, g_sT_hi);

    float* logp = out;
    if (out_size >= 2 * NROWS * FHID) embed = out + (size_t)NROWS * FHID;
    else cudaGetSymbolAddress((void**)&embed, g_embed_fallback);

    cudaFuncSetAttribute(gemm2_hmma, cudaFuncAttributeMaxDynamicSharedMemorySize, 2 * STG2);

    // 1) support = x @ W (fp32)
    sgemm_n256<<<NROWS / BM, 256>>>(x, W, support, FIN);
    // 2) supportT -> fp16, [FHID][NROWS]
    transpose_half<<<dim3(NROWS / 32, FHID / 32), 256>>>(support, sTh);
    // 3) embed = adj @ support + b  (HMMA 2-term split on A)
    gemm2_hmma<<<NROWS / BM2, 256, 2 * STG2>>>(adj, sTh, b, embed);
    // 4) logp = log_softmax(embed)
    row_logsoftmax<<<NROWS, 256>>>(embed, logp);
}

// round 5
// speedup vs baseline: 5.6106x; 1.6063x over previous
#include <cuda_runtime.h>
#include <cuda_fp16.h>
#include <math.h>
#include <stdint.h>

#define NROWS 16384
#define FIN   512
#define FHID  256

// ---------------- scratch (__device__ globals; no allocation) ----------------
__device__ float  g_support[(size_t)NROWS * FHID];        // 16 MiB fp32
__device__ __half g_sT[(size_t)FHID * NROWS];             // 8 MiB  supportT (fp16)
__device__ float  g_embed_fallback[(size_t)NROWS * FHID];

// ---------------- asm helpers (arch-neutral PTX, sm_80+) ----------------
__device__ __forceinline__ uint32_t smem_u32(const void* p) {
    uint32_t a;
    asm("{ .reg .u64 t; cvta.to.shared.u64 t, %1; cvt.u32.u64 %0, t; }" : "=r"(a) : "l"(p));
    return a;
}
#define CP_ASYNC16(dst, src) \
    asm volatile("cp.async.cg.shared.global [%0], [%1], 16;" :: "r"(dst), "l"(src))
#define CP_COMMIT() asm volatile("cp.async.commit_group;" ::: "memory")
#define CP_WAIT1()  asm volatile("cp.async.wait_group 1;" ::: "memory")
#define CP_WAIT0()  asm volatile("cp.async.wait_group 0;" ::: "memory")
#define LDSM4(r, a) \
    asm volatile("ldmatrix.sync.aligned.m8n8.x4.shared.b16 {%0,%1,%2,%3}, [%4];" \
        : "=r"((r)[0]), "=r"((r)[1]), "=r"((r)[2]), "=r"((r)[3]) : "r"(a))
#define MMA16816(c, a, b) \
    asm volatile("mma.sync.aligned.m16n8k16.row.col.f32.f16.f16.f32 " \
        "{%0,%1,%2,%3}, {%4,%5,%6,%7}, {%8,%9}, {%0,%1,%2,%3};" \
        : "+f"((c)[0]), "+f"((c)[1]), "+f"((c)[2]), "+f"((c)[3]) \
        : "r"((a)[0]), "r"((a)[1]), "r"((a)[2]), "r"((a)[3]), "r"((b)[0]), "r"((b)[1]))

// ================= GEMM1: support = x @ W (fp32 FFMA, proven) =================
#define BM 64
#define BN 256
#define BK 16
#define TM 8
#define TN 8
#define APAD 4

__global__ __launch_bounds__(256, 2)
void sgemm_n256(const float* __restrict__ A, const float* __restrict__ B,
                float* __restrict__ C, int Kdim)
{
    __shared__ float As[BK][BM + APAD];
    __shared__ float Bs[BK][BN];
    const int tid = threadIdx.x, blockRow = blockIdx.x;
    const int tRow = tid >> 5, tCol = tid & 31;
    const float* Ab = A + (size_t)blockRow * BM * Kdim;
    float acc[TM][TN];
    #pragma unroll
    for (int i = 0; i < TM; i++)
        #pragma unroll
        for (int j = 0; j < TN; j++) acc[i][j] = 0.0f;
    const int aRow = tid >> 2, aCol4 = (tid & 3) * 4;
    const int bRow = tid >> 6, bCol4 = (tid & 63) * 4;
    for (int k0 = 0; k0 < Kdim; k0 += BK) {
        float4 av = *reinterpret_cast<const float4*>(Ab + (size_t)aRow * Kdim + (k0 + aCol4));
        As[aCol4 + 0][aRow] = av.x; As[aCol4 + 1][aRow] = av.y;
        As[aCol4 + 2][aRow] = av.z; As[aCol4 + 3][aRow] = av.w;
        #pragma unroll
        for (int p = 0; p < 4; p++) {
            int r = bRow + p * 4;
            *reinterpret_cast<float4*>(&Bs[r][bCol4]) =
                *reinterpret_cast<const float4*>(B + (size_t)(k0 + r) * BN + bCol4);
        }
        __syncthreads();
        #pragma unroll
        for (int k = 0; k < BK; k++) {
            float ra[TM], rb[TN];
            #pragma unroll
            for (int i = 0; i < TM; i++) ra[i] = As[k][tRow * TM + i];
            float4 b0 = *reinterpret_cast<const float4*>(&Bs[k][tCol * 4]);
            float4 b1 = *reinterpret_cast<const float4*>(&Bs[k][128 + tCol * 4]);
            rb[0]=b0.x; rb[1]=b0.y; rb[2]=b0.z; rb[3]=b0.w;
            rb[4]=b1.x; rb[5]=b1.y; rb[6]=b1.z; rb[7]=b1.w;
            #pragma unroll
            for (int i = 0; i < TM; i++)
                #pragma unroll
                for (int j = 0; j < TN; j++) acc[i][j] = fmaf(ra[i], rb[j], acc[i][j]);
        }
        __syncthreads();
    }
    #pragma unroll
    for (int i = 0; i < TM; i++) {
        int gr = blockRow * BM + tRow * TM + i;
        float* Crow = C + (size_t)gr * BN;
        *reinterpret_cast<float4*>(Crow + tCol * 4) =
            make_float4(acc[i][0], acc[i][1], acc[i][2], acc[i][3]);
        *reinterpret_cast<float4*>(Crow + 128 + tCol * 4) =
            make_float4(acc[i][4], acc[i][5], acc[i][6], acc[i][7]);
    }
}

// ====== transpose + fp16 round: sT[h][n] = fp16(support[n][h]) ======
__global__ __launch_bounds__(256)
void transpose_half(const float* __restrict__ S, __half* __restrict__ Th)
{
    __shared__ float ts[32][33];
    const int n0 = blockIdx.x * 32, h0 = blockIdx.y * 32;
    const int tx = threadIdx.x & 31, ty = threadIdx.x >> 5;  // 32 x 8
    #pragma unroll
    for (int k = 0; k < 4; k++)
        ts[ty + 8 * k][tx] = S[(size_t)(n0 + ty + 8 * k) * FHID + h0 + tx];
    __syncthreads();
    #pragma unroll
    for (int k = 0; k < 4; k++) {
        int h = h0 + ty + 8 * k, n = n0 + tx;
        Th[(size_t)h * NROWS + n] = __float2half_rn(ts[tx][ty + 8 * k]);
    }
}

// ============ GEMM2: embed = adj @ support + b  (HMMA, single fp16 term) ============
// BM2=64, BN=256(=FHID: adj streamed once), BK2=64, 256 threads = 8 warps (2Mx4N),
// warptile 32x64, occ 2. Double-buffered smem; B via cp.async; A fp32->fp16 in regs.
#define BM2 64
#define BK2 64
#define LDS2 72                    // halves per smem row (8-half pad), pitch 144B
#define SB_OFF 0
#define SA_OFF 36864               // 256*144
#define STG2  46080                // + 64*144
#define NCH2  (NROWS / BK2)        // 256 chunks

__global__ __launch_bounds__(256, 2)
void gemm2_hmma(const float* __restrict__ adj,
                const __half* __restrict__ Bh,
                const float* __restrict__ bias,
                float* __restrict__ embed)
{
    extern __shared__ char sm[];
    const uint32_t sb = smem_u32(sm);
    const int tid  = threadIdx.x;
    const int lane = tid & 31, wid = tid >> 5;
    const int wm = wid >> 2, wn = wid & 3;       // 2 x 4 warp grid
    const int mblk = blockIdx.x * BM2;

    float acc[2][8][4];
    #pragma unroll
    for (int i = 0; i < 2; i++)
        #pragma unroll
        for (int j = 0; j < 8; j++)
            #pragma unroll
            for (int q = 0; q < 4; q++) acc[i][j][q] = 0.0f;

    // ---- cp.async B tile: 256 rows x 64 halves = 32KB; 8 x 16B per thread ----
    auto issueB = [&](int c, int s) {
        const size_t k0 = (size_t)c * BK2;
        #pragma unroll
        for (int i = 0; i < 8; i++) {
            int o = tid + i * 256;
            int row = o >> 3, kc = o & 7;
            const __half* src = Bh + (size_t)row * NROWS + k0 + kc * 8;
            uint32_t off = (uint32_t)(row * 144 + kc * 16);
            CP_ASYNC16(sb + s * STG2 + SB_OFF + off, src);
        }
    };
    // ---- A: 64 rows x 64 fp32 = 16KB; 8 floats (2 float4) per thread x2 ----
    auto ldgA = [&](int c, float4 av[2][2]) {
        #pragma unroll
        for (int i = 0; i < 2; i++) {
            int o = tid + i * 256;
            int row = o >> 3, seg = o & 7;
            const float* p = adj + (size_t)(mblk + row) * NROWS + (size_t)c * BK2 + seg * 8;
            av[i][0] = *reinterpret_cast<const float4*>(p);
            av[i][1] = *reinterpret_cast<const float4*>(p + 4);
        }
    };
    auto storeA = [&](const float4 av[2][2], int s) {
        #pragma unroll
        for (int i = 0; i < 2; i++) {
            int o = tid + i * 256;
            int row = o >> 3, seg = o & 7;
            __half2 h0 = __float22half2_rn(make_float2(av[i][0].x, av[i][0].y));
            __half2 h1 = __float22half2_rn(make_float2(av[i][0].z, av[i][0].w));
            __half2 h2 = __float22half2_rn(make_float2(av[i][1].x, av[i][1].y));
            __half2 h3 = __float22half2_rn(make_float2(av[i][1].z, av[i][1].w));
            uint32_t off = (uint32_t)(row * 144 + seg * 16);
            *reinterpret_cast<uint4*>(sm + s * STG2 + SA_OFF + off) =
                make_uint4(*reinterpret_cast<uint32_t*>(&h0), *reinterpret_cast<uint32_t*>(&h1),
                           *reinterpret_cast<uint32_t*>(&h2), *reinterpret_cast<uint32_t*>(&h3));
        }
    };
    auto compute = [&](int s) {
        const uint32_t base = sb + s * STG2;
        #pragma unroll
        for (int kk = 0; kk < 4; kk++) {
            uint32_t ah[2][4];
            const int arow = lane & 15;
            const int acol = kk * 16 + (lane >> 4) * 8;
            #pragma unroll
            for (int mi = 0; mi < 2; mi++) {
                uint32_t ao = (uint32_t)((wm * 32 + mi * 16 + arow) * 144 + acol * 2);
                LDSM4(ah[mi], base + SA_OFF + ao);
            }
            #pragma unroll
            for (int g = 0; g < 4; g++) {
                const int nrow = wn * 64 + g * 16 + (lane & 7) + ((lane >> 4) << 3);
                const int ncol = kk * 16 + ((lane >> 3) & 1) * 8;
                uint32_t bo = (uint32_t)(nrow * 144 + ncol * 2);
                uint32_t bh[4];
                LDSM4(bh, base + SB_OFF + bo);
                #pragma unroll
                for (int mi = 0; mi < 2; mi++)
                    #pragma unroll
                    for (int q = 0; q < 2; q++)
                        MMA16816(acc[mi][g * 2 + q], ah[mi], &bh[2 * q]);
            }
        }
    };

    // ---- prologue ----
    float4 av[2][2];
    issueB(0, 0); CP_COMMIT();
    ldgA(0, av);  storeA(av, 0);
    issueB(1, 1); CP_COMMIT();

    // ---- mainloop ----
    for (int c = 0; c < NCH2; ++c) {
        const bool more = (c + 1 < NCH2);
        if (more) ldgA(c + 1, av);
        if (more) CP_WAIT1(); else CP_WAIT0();
        __syncthreads();
        compute(c & 1);
        if (more) storeA(av, (c + 1) & 1);
        __syncthreads();
        if (c + 2 < NCH2) { issueB(c + 2, c & 1); CP_COMMIT(); }
    }

    // ---- epilogue: + bias, store embed ----
    #pragma unroll
    for (int ni = 0; ni < 8; ni++) {
        const int col = wn * 64 + ni * 8 + (lane & 3) * 2;
        const float2 bv = *reinterpret_cast<const float2*>(bias + col);
        #pragma unroll
        for (int mi = 0; mi < 2; mi++) {
            const int r0 = mblk + wm * 32 + mi * 16 + (lane >> 2);
            const float* c = acc[mi][ni];
            *reinterpret_cast<float2*>(embed + (size_t)r0 * FHID + col) =
                make_float2(c[0] + bv.x, c[1] + bv.y);
            *reinterpret_cast<float2*>(embed + (size_t)(r0 + 8) * FHID + col) =
                make_float2(c[2] + bv.x, c[3] + bv.y);
        }
    }
}

// ---------------- row-wise log_softmax over FHID=256 ----------------
__global__ __launch_bounds__(256)
void row_logsoftmax(const float* __restrict__ E, float* __restrict__ P)
{
    const int row = blockIdx.x;
    const int t   = threadIdx.x;
    const float v = E[(size_t)row * FHID + t];
    __shared__ float smax[8];
    __shared__ float ssum[8];
    float m = v;
    #pragma unroll
    for (int o = 16; o > 0; o >>= 1)
        m = fmaxf(m, __shfl_xor_sync(0xffffffffu, m, o));
    if ((t & 31) == 0) smax[t >> 5] = m;
    __syncthreads();
    float mm = smax[0];
    #pragma unroll
    for (int w = 1; w < 8; w++) mm = fmaxf(mm, smax[w]);
    float ex = expf(v - mm);
    float s = ex;
    #pragma unroll
    for (int o = 16; o > 0; o >>= 1)
        s += __shfl_xor_sync(0xffffffffu, s, o);
    if ((t & 31) == 0) ssum[t >> 5] = s;
    __syncthreads();
    float tot = 0.0f;
    #pragma unroll
    for (int w = 0; w < 8; w++) tot += ssum[w];
    const float lse = mm + logf(tot);
    P[(size_t)row * FHID + t] = v - lse;
}

// ================= launch =================
extern "C" void kernel_launch(void* const* d_in, const int* in_sizes, int n_in,
                              void* d_out, int out_size)
{
    const float* x   = (const float*)d_in[0];
    const float* adj = (const float*)d_in[1];
    const float* W   = (const float*)d_in[2];
    const float* b   = (const float*)d_in[3];
    float* out = (float*)d_out;

    float *support, *embed;
    __half *sT;
    cudaGetSymbolAddress((void**)&support, g_support);
    cudaGetSymbolAddress((void**)&sT, g_sT);

    float* logp = out;
    if (out_size >= 2 * NROWS * FHID) embed = out + (size_t)NROWS * FHID;
    else cudaGetSymbolAddress((void**)&embed, g_embed_fallback);

    cudaFuncSetAttribute(gemm2_hmma, cudaFuncAttributeMaxDynamicSharedMemorySize, 2 * STG2);

    // 1) support = x @ W (fp32)
    sgemm_n256<<<NROWS / BM, 256>>>(x, W, support, FIN);
    // 2) supportT -> fp16, [FHID][NROWS]
    transpose_half<<<dim3(NROWS / 32, FHID / 32), 256>>>(support, sT);
    // 3) embed = adj @ support + b  (HMMA single-term)
    gemm2_hmma<<<NROWS / BM2, 256, 2 * STG2>>>(adj, sT, b, embed);
    // 4) logp = log_softmax(embed)
    row_logsoftmax<<<NROWS, 256>>>(embed, logp);
}

// round 6
// speedup vs baseline: 5.6619x; 1.0091x over previous
#include <cuda_runtime.h>
#include <cuda_fp16.h>
#include <math.h>
#include <stdint.h>

#define NROWS 16384
#define FIN   512
#define FHID  256

// ---------------- scratch (__device__ globals; no allocation) ----------------
__device__ float  g_support[(size_t)NROWS * FHID];        // 16 MiB fp32
__device__ __half g_sT[(size_t)FHID * NROWS];             // 8 MiB  supportT (fp16)
__device__ float  g_embed_fallback[(size_t)NROWS * FHID];

// ---------------- asm helpers (arch-neutral PTX, sm_80+) ----------------
__device__ __forceinline__ uint32_t smem_u32(const void* p) {
    uint32_t a;
    asm("{ .reg .u64 t; cvta.to.shared.u64 t, %1; cvt.u32.u64 %0, t; }" : "=r"(a) : "l"(p));
    return a;
}
#define CP_ASYNC16(dst, src) \
    asm volatile("cp.async.cg.shared.global [%0], [%1], 16;" :: "r"(dst), "l"(src))
#define CP_COMMIT() asm volatile("cp.async.commit_group;" ::: "memory")
#define CP_WAIT1()  asm volatile("cp.async.wait_group 1;" ::: "memory")
#define CP_WAIT0()  asm volatile("cp.async.wait_group 0;" ::: "memory")
#define LDSM4(r, a) \
    asm volatile("ldmatrix.sync.aligned.m8n8.x4.shared.b16 {%0,%1,%2,%3}, [%4];" \
        : "=r"((r)[0]), "=r"((r)[1]), "=r"((r)[2]), "=r"((r)[3]) : "r"(a))
#define MMA16816(c, a, b) \
    asm volatile("mma.sync.aligned.m16n8k16.row.col.f32.f16.f16.f32 " \
        "{%0,%1,%2,%3}, {%4,%5,%6,%7}, {%8,%9}, {%0,%1,%2,%3};" \
        : "+f"((c)[0]), "+f"((c)[1]), "+f"((c)[2]), "+f"((c)[3]) \
        : "r"((a)[0]), "r"((a)[1]), "r"((a)[2]), "r"((a)[3]), "r"((b)[0]), "r"((b)[1]))

// ================= GEMM1: support = x @ W (fp32 FFMA, proven) =================
#define BM 64
#define BN 256
#define BK 16
#define TM 8
#define TN 8
#define APAD 4

__global__ __launch_bounds__(256, 2)
void sgemm_n256(const float* __restrict__ A, const float* __restrict__ B,
                float* __restrict__ C, int Kdim)
{
    __shared__ float As[BK][BM + APAD];
    __shared__ float Bs[BK][BN];
    const int tid = threadIdx.x, blockRow = blockIdx.x;
    const int tRow = tid >> 5, tCol = tid & 31;
    const float* Ab = A + (size_t)blockRow * BM * Kdim;
    float acc[TM][TN];
    #pragma unroll
    for (int i = 0; i < TM; i++)
        #pragma unroll
        for (int j = 0; j < TN; j++) acc[i][j] = 0.0f;
    const int aRow = tid >> 2, aCol4 = (tid & 3) * 4;
    const int bRow = tid >> 6, bCol4 = (tid & 63) * 4;
    for (int k0 = 0; k0 < Kdim; k0 += BK) {
        float4 av = *reinterpret_cast<const float4*>(Ab + (size_t)aRow * Kdim + (k0 + aCol4));
        As[aCol4 + 0][aRow] = av.x; As[aCol4 + 1][aRow] = av.y;
        As[aCol4 + 2][aRow] = av.z; As[aCol4 + 3][aRow] = av.w;
        #pragma unroll
        for (int p = 0; p < 4; p++) {
            int r = bRow + p * 4;
            *reinterpret_cast<float4*>(&Bs[r][bCol4]) =
                *reinterpret_cast<const float4*>(B + (size_t)(k0 + r) * BN + bCol4);
        }
        __syncthreads();
        #pragma unroll
        for (int k = 0; k < BK; k++) {
            float ra[TM], rb[TN];
            #pragma unroll
            for (int i = 0; i < TM; i++) ra[i] = As[k][tRow * TM + i];
            float4 b0 = *reinterpret_cast<const float4*>(&Bs[k][tCol * 4]);
            float4 b1 = *reinterpret_cast<const float4*>(&Bs[k][128 + tCol * 4]);
            rb[0]=b0.x; rb[1]=b0.y; rb[2]=b0.z; rb[3]=b0.w;
            rb[4]=b1.x; rb[5]=b1.y; rb[6]=b1.z; rb[7]=b1.w;
            #pragma unroll
            for (int i = 0; i < TM; i++)
                #pragma unroll
                for (int j = 0; j < TN; j++) acc[i][j] = fmaf(ra[i], rb[j], acc[i][j]);
        }
        __syncthreads();
    }
    #pragma unroll
    for (int i = 0; i < TM; i++) {
        int gr = blockRow * BM + tRow * TM + i;
        float* Crow = C + (size_t)gr * BN;
        *reinterpret_cast<float4*>(Crow + tCol * 4) =
            make_float4(acc[i][0], acc[i][1], acc[i][2], acc[i][3]);
        *reinterpret_cast<float4*>(Crow + 128 + tCol * 4) =
            make_float4(acc[i][4], acc[i][5], acc[i][6], acc[i][7]);
    }
}

// ====== transpose + fp16 round: sT[h][n] = fp16(support[n][h]) ======
__global__ __launch_bounds__(256)
void transpose_half(const float* __restrict__ S, __half* __restrict__ Th)
{
    __shared__ float ts[32][33];
    const int n0 = blockIdx.x * 32, h0 = blockIdx.y * 32;
    const int tx = threadIdx.x & 31, ty = threadIdx.x >> 5;  // 32 x 8
    #pragma unroll
    for (int k = 0; k < 4; k++)
        ts[ty + 8 * k][tx] = S[(size_t)(n0 + ty + 8 * k) * FHID + h0 + tx];
    __syncthreads();
    #pragma unroll
    for (int k = 0; k < 4; k++) {
        int h = h0 + ty + 8 * k, n = n0 + tx;
        Th[(size_t)h * NROWS + n] = __float2half_rn(ts[tx][ty + 8 * k]);
    }
}

// ===== GEMM2 + bias + log_softmax fused (HMMA single fp16 term) =====
// BM2=64, BN=256(=FHID), BK2=64, 256 threads = 8 warps (2Mx4N), warptile 32x64.
// Smem: 3-stage B (XOR-swizzled, pitch 128B) + 2-stage A; ONE barrier per chunk.
#define BM2 64
#define BK2 64
#define SBST 32768                 // B stage: 256 rows * 128B
#define SA_OFF (3 * SBST)          // 98304
#define SAST 8192                  // A stage: 64 rows * 128B
#define G2_SMEM (SA_OFF + 2 * SAST)// 114688
#define NCH2  (NROWS / BK2)        // 256 chunks

__global__ __launch_bounds__(256, 2)
void gemm2_fused(const float* __restrict__ adj,
                 const __half* __restrict__ Bh,
                 const float* __restrict__ bias,
                 float* __restrict__ embed,
                 float* __restrict__ logp)
{
    extern __shared__ char sm[];
    const uint32_t sb = smem_u32(sm);
    const int tid  = threadIdx.x;
    const int lane = tid & 31, wid = tid >> 5;
    const int wm = wid >> 2, wn = wid & 3;       // 2 x 4 warp grid
    const int mblk = blockIdx.x * BM2;

    float acc[2][8][4];
    #pragma unroll
    for (int i = 0; i < 2; i++)
        #pragma unroll
        for (int j = 0; j < 8; j++)
            #pragma unroll
            for (int q = 0; q < 4; q++) acc[i][j][q] = 0.0f;

    // ---- B tile via cp.async: 256 rows x 64 halves (128B/row), xor-swizzled ----
    auto issueB = [&](int c, int s) {
        const size_t k0 = (size_t)c * BK2;
        #pragma unroll
        for (int i = 0; i < 8; i++) {
            int o = tid + i * 256;
            int row = o >> 3, kc = o & 7;
            const __half* src = Bh + (size_t)row * NROWS + k0 + kc * 8;
            uint32_t dst = sb + (uint32_t)s * SBST + (uint32_t)row * 128
                         + (uint32_t)((kc ^ (row & 7)) << 4);
            CP_ASYNC16(dst, src);
        }
    };
    // ---- A: 64 rows x 64 fp32; thread owns (row = tid>>2, 16-col seg q = tid&3) ----
    const int arow_ = tid >> 2, aq = tid & 3;
    auto ldgA = [&](int c, float4 av[4]) {
        const float* p = adj + (size_t)(mblk + arow_) * NROWS + (size_t)c * BK2 + aq * 16;
        av[0] = reinterpret_cast<const float4*>(p)[0];
        av[1] = reinterpret_cast<const float4*>(p)[1];
        av[2] = reinterpret_cast<const float4*>(p)[2];
        av[3] = reinterpret_cast<const float4*>(p)[3];
    };
    auto storeA = [&](const float4 av[4], int d) {
        uint32_t w[8];
        #pragma unroll
        for (int i = 0; i < 4; i++) {
            __half2 h0 = __float22half2_rn(make_float2(av[i].x, av[i].y));
            __half2 h1 = __float22half2_rn(make_float2(av[i].z, av[i].w));
            w[2 * i]     = *reinterpret_cast<uint32_t*>(&h0);
            w[2 * i + 1] = *reinterpret_cast<uint32_t*>(&h1);
        }
        uint32_t base = sb + SA_OFF + (uint32_t)d * SAST + (uint32_t)arow_ * 128;
        uint32_t u0 = (uint32_t)((aq * 2) ^ (arow_ & 7)) << 4;
        uint32_t u1 = (uint32_t)((aq * 2 + 1) ^ (arow_ & 7)) << 4;
        asm volatile("st.shared.v4.b32 [%0], {%1,%2,%3,%4};" ::
            "r"(base + u0), "r"(w[0]), "r"(w[1]), "r"(w[2]), "r"(w[3]));
        asm volatile("st.shared.v4.b32 [%0], {%1,%2,%3,%4};" ::
            "r"(base + u1), "r"(w[4]), "r"(w[5]), "r"(w[6]), "r"(w[7]));
    };
    auto compute = [&](int bs, int ad) {
        const uint32_t baseB = sb + (uint32_t)bs * SBST;
        const uint32_t baseA = sb + SA_OFF + (uint32_t)ad * SAST;
        #pragma unroll
        for (int kk = 0; kk < 4; kk++) {
            uint32_t ah[2][4];
            const int arow = lane & 15;
            const int uA = kk * 2 + (lane >> 4);
            #pragma unroll
            for (int mi = 0; mi < 2; mi++) {
                int r = wm * 32 + mi * 16 + arow;
                LDSM4(ah[mi], baseA + (uint32_t)r * 128 + (uint32_t)((uA ^ (r & 7)) << 4));
            }
            #pragma unroll
            for (int g = 0; g < 4; g++) {
                const int nrow = wn * 64 + g * 16 + (lane & 7) + ((lane >> 4) << 3);
                const int uB = kk * 2 + ((lane >> 3) & 1);
                uint32_t bh[4];
                LDSM4(bh, baseB + (uint32_t)nrow * 128 + (uint32_t)((uB ^ (nrow & 7)) << 4));
                #pragma unroll
                for (int mi = 0; mi < 2; mi++)
                    #pragma unroll
                    for (int q = 0; q < 2; q++)
                        MMA16816(acc[mi][g * 2 + q], ah[mi], &bh[2 * q]);
            }
        }
    };

    // ---- prologue ----
    issueB(0, 0); CP_COMMIT();
    issueB(1, 1); CP_COMMIT();
    float4 av[4];
    ldgA(0, av); storeA(av, 0);
    ldgA(1, av);

    // ---- mainloop: ONE barrier per chunk ----
    // iter c: top sync separates (a) compute(c-1) reads of A-buf (c+1)&1 and
    // B-stage (c+2)%3 from this iter's overwrites, (b) makes storeA(c) visible.
    for (int c = 0; c < NCH2; ++c) {
        if (c < NCH2 - 1) CP_WAIT1(); else CP_WAIT0();
        __syncthreads();
        if (c + 1 < NCH2) storeA(av, (c + 1) & 1);
        compute(c % 3, c & 1);
        if (c + 2 < NCH2) { issueB(c + 2, (c + 2) % 3); CP_COMMIT(); }
        if (c + 2 < NCH2) ldgA(c + 2, av);
    }
    __syncthreads();   // stage smem now reusable for softmax partials

    // ---- epilogue: bias + row-wise log_softmax + stores ----
    // acc[mi][ni][0,1] = row r0 cols c,c+1 ; acc[mi][ni][2,3] = row r0+8.
    #pragma unroll
    for (int ni = 0; ni < 8; ni++) {
        const float2 bv = __ldg(reinterpret_cast<const float2*>(
            bias + wn * 64 + ni * 8 + (lane & 3) * 2));
        #pragma unroll
        for (int mi = 0; mi < 2; mi++) {
            acc[mi][ni][0] += bv.x; acc[mi][ni][1] += bv.y;
            acc[mi][ni][2] += bv.x; acc[mi][ni][3] += bv.y;
        }
    }
    float* part  = reinterpret_cast<float*>(sm);          // [64][4]
    float* part2 = reinterpret_cast<float*>(sm + 1024);   // [64][4]
    float mx[2][2];
    #pragma unroll
    for (int mi = 0; mi < 2; mi++)
        #pragma unroll
        for (int rh = 0; rh < 2; rh++) {
            float m = -INFINITY;
            #pragma unroll
            for (int ni = 0; ni < 8; ni++)
                m = fmaxf(m, fmaxf(acc[mi][ni][rh * 2], acc[mi][ni][rh * 2 + 1]));
            m = fmaxf(m, __shfl_xor_sync(0xffffffffu, m, 1));
            m = fmaxf(m, __shfl_xor_sync(0xffffffffu, m, 2));
            mx[mi][rh] = m;
        }
    if ((lane & 3) == 0) {
        #pragma unroll
        for (int mi = 0; mi < 2; mi++)
            #pragma unroll
            for (int rh = 0; rh < 2; rh++)
                part[(wm * 32 + mi * 16 + (lane >> 2) + rh * 8) * 4 + wn] = mx[mi][rh];
    }
    __syncthreads();
    float rmax[2][2];
    #pragma unroll
    for (int mi = 0; mi < 2; mi++)
        #pragma unroll
        for (int rh = 0; rh < 2; rh++) {
            int r = wm * 32 + mi * 16 + (lane >> 2) + rh * 8;
            rmax[mi][rh] = fmaxf(fmaxf(part[r * 4], part[r * 4 + 1]),
                                 fmaxf(part[r * 4 + 2], part[r * 4 + 3]));
        }
    float sme[2][2];
    #pragma unroll
    for (int mi = 0; mi < 2; mi++)
        #pragma unroll
        for (int rh = 0; rh < 2; rh++) {
            float s = 0.0f;
            #pragma unroll
            for (int ni = 0; ni < 8; ni++)
                s += __expf(acc[mi][ni][rh * 2] - rmax[mi][rh])
                   + __expf(acc[mi][ni][rh * 2 + 1] - rmax[mi][rh]);
            s += __shfl_xor_sync(0xffffffffu, s, 1);
            s += __shfl_xor_sync(0xffffffffu, s, 2);
            sme[mi][rh] = s;
        }
    if ((lane & 3) == 0) {
        #pragma unroll
        for (int mi = 0; mi < 2; mi++)
            #pragma unroll
            for (int rh = 0; rh < 2; rh++)
                part2[(wm * 32 + mi * 16 + (lane >> 2) + rh * 8) * 4 + wn] = sme[mi][rh];
    }
    __syncthreads();
    float lse[2][2];
    #pragma unroll
    for (int mi = 0; mi < 2; mi++)
        #pragma unroll
        for (int rh = 0; rh < 2; rh++) {
            int r = wm * 32 + mi * 16 + (lane >> 2) + rh * 8;
            lse[mi][rh] = rmax[mi][rh] + __logf(part2[r * 4] + part2[r * 4 + 1]
                                              + part2[r * 4 + 2] + part2[r * 4 + 3]);
        }
    #pragma unroll
    for (int ni = 0; ni < 8; ni++) {
        const int col = wn * 64 + ni * 8 + (lane & 3) * 2;
        #pragma unroll
        for (int mi = 0; mi < 2; mi++) {
            const int r0 = mblk + wm * 32 + mi * 16 + (lane >> 2);
            const float* c = acc[mi][ni];
            *reinterpret_cast<float2*>(embed + (size_t)r0 * FHID + col) =
                make_float2(c[0], c[1]);
            *reinterpret_cast<float2*>(embed + (size_t)(r0 + 8) * FHID + col) =
                make_float2(c[2], c[3]);
            *reinterpret_cast<float2*>(logp + (size_t)r0 * FHID + col) =
                make_float2(c[0] - lse[mi][0], c[1] - lse[mi][0]);
            *reinterpret_cast<float2*>(logp + (size_t)(r0 + 8) * FHID + col) =
                make_float2(c[2] - lse[mi][1], c[3] - lse[mi][1]);
        }
    }
}

// ================= launch =================
extern "C" void kernel_launch(void* const* d_in, const int* in_sizes, int n_in,
                              void* d_out, int out_size)
{
    const float* x   = (const float*)d_in[0];
    const float* adj = (const float*)d_in[1];
    const float* W   = (const float*)d_in[2];
    const float* b   = (const float*)d_in[3];
    float* out = (float*)d_out;

    float *support, *embed;
    __half *sT;
    cudaGetSymbolAddress((void**)&support, g_support);
    cudaGetSymbolAddress((void**)&sT, g_sT);

    float* logp = out;
    if (out_size >= 2 * NROWS * FHID) embed = out + (size_t)NROWS * FHID;
    else cudaGetSymbolAddress((void**)&embed, g_embed_fallback);

    cudaFuncSetAttribute(gemm2_fused, cudaFuncAttributeMaxDynamicSharedMemorySize, G2_SMEM);

    // 1) support = x @ W (fp32)
    sgemm_n256<<<NROWS / BM, 256>>>(x, W, support, FIN);
    // 2) supportT -> fp16, [FHID][NROWS]
    transpose_half<<<dim3(NROWS / 32, FHID / 32), 256>>>(support, sT);
    // 3) embed = adj @ support + b ; logp = log_softmax(embed)   [fused]
    gemm2_fused<<<NROWS / BM2, 256, G2_SMEM>>>(adj, sT, b, embed, logp);
}

// round 7
// speedup vs baseline: 6.4168x; 1.1333x over previous
#include <cuda_runtime.h>
#include <cuda_fp16.h>
#include <math.h>
#include <stdint.h>

#define NROWS 16384
#define FIN   512
#define FHID  256

// ---------------- scratch (__device__ globals; no allocation) ----------------
__device__ __half g_xh [(size_t)NROWS * FIN];     // 16 MiB  x in fp16
__device__ __half g_WTh[(size_t)FHID * FIN];      // 256 KiB Wᵀ hi
__device__ __half g_WTl[(size_t)FHID * FIN];      // 256 KiB Wᵀ lo
__device__ __half g_sT [(size_t)FHID * NROWS];    // 8 MiB   supportᵀ fp16
__device__ float  g_embed_fallback[(size_t)NROWS * FHID];

// ---------------- asm helpers (arch-neutral PTX, sm_80+) ----------------
__device__ __forceinline__ uint32_t smem_u32(const void* p) {
    uint32_t a;
    asm("{ .reg .u64 t; cvta.to.shared.u64 t, %1; cvt.u32.u64 %0, t; }" : "=r"(a) : "l"(p));
    return a;
}
#define CP_ASYNC16(dst, src) \
    asm volatile("cp.async.cg.shared.global [%0], [%1], 16;" :: "r"(dst), "l"(src))
#define CP_COMMIT() asm volatile("cp.async.commit_group;" ::: "memory")
#define CP_WAIT1()  asm volatile("cp.async.wait_group 1;" ::: "memory")
#define CP_WAIT0()  asm volatile("cp.async.wait_group 0;" ::: "memory")
#define LDSM4(r, a) \
    asm volatile("ldmatrix.sync.aligned.m8n8.x4.shared.b16 {%0,%1,%2,%3}, [%4];" \
        : "=r"((r)[0]), "=r"((r)[1]), "=r"((r)[2]), "=r"((r)[3]) : "r"(a))
#define MMA16816(c, a, b) \
    asm volatile("mma.sync.aligned.m16n8k16.row.col.f32.f16.f16.f32 " \
        "{%0,%1,%2,%3}, {%4,%5,%6,%7}, {%8,%9}, {%0,%1,%2,%3};" \
        : "+f"((c)[0]), "+f"((c)[1]), "+f"((c)[2]), "+f"((c)[3]) \
        : "r"((a)[0]), "r"((a)[1]), "r"((a)[2]), "r"((a)[3]), "r"((b)[0]), "r"((b)[1]))

// ====== prep 1: W [512,256] fp32 -> WT hi/lo [256,512] fp16 ======
__global__ __launch_bounds__(256)
void wt_split(const float* __restrict__ W, __half* __restrict__ Th, __half* __restrict__ Tl)
{
    __shared__ float ts[32][33];
    const int f0 = blockIdx.x * 32, h0 = blockIdx.y * 32;
    const int tx = threadIdx.x & 31, ty = threadIdx.x >> 5;  // 32 x 8
    #pragma unroll
    for (int k = 0; k < 4; k++)
        ts[ty + 8 * k][tx] = W[(size_t)(f0 + ty + 8 * k) * FHID + h0 + tx];
    __syncthreads();
    #pragma unroll
    for (int k = 0; k < 4; k++) {
        int h = h0 + ty + 8 * k, f = f0 + tx;
        float v = ts[tx][ty + 8 * k];
        __half hb = __float2half_rn(v);
        __half lb = __float2half_rn(v - __half2float(hb));
        Th[(size_t)h * FIN + f] = hb;
        Tl[(size_t)h * FIN + f] = lb;
    }
}

// ====== prep 2: x fp32 -> fp16 elementwise ======
__global__ __launch_bounds__(256)
void x_half(const float* __restrict__ X, __half* __restrict__ Xh)
{
    size_t i = ((size_t)blockIdx.x * 256 + threadIdx.x) * 4;
    float4 v = *reinterpret_cast<const float4*>(X + i);
    __half2 h0 = __float22half2_rn(make_float2(v.x, v.y));
    __half2 h1 = __float22half2_rn(make_float2(v.z, v.w));
    *reinterpret_cast<uint2*>(Xh + i) =
        make_uint2(*reinterpret_cast<uint32_t*>(&h0), *reinterpret_cast<uint32_t*>(&h1));
}

// ====== GEMM1 (HMMA): sT[h][n] = (WT hi+lo) @ x_fp16, output fp16 ======
// grid (FHID/64, NROWS/256); 256 thr = 8 warps (2Mx4N), warptile 32x64, BK=64.
#define G1_SBST 32768                    // B stage: 256 rows * 128B
#define G1_SA   (2 * G1_SBST)            // A stages after B's two
#define G1_SAST 16384                    // A stage: hi 8192 + lo 8192
#define G1_SMEM (G1_SA + 2 * G1_SAST)    // 98304
#define NCH1 (FIN / 64)                  // 8 chunks

__global__ __launch_bounds__(256, 2)
void gemm1_hmma(const __half* __restrict__ WTh, const __half* __restrict__ WTl,
                const __half* __restrict__ Xh, __half* __restrict__ sT)
{
    extern __shared__ char sm[];
    const uint32_t sb = smem_u32(sm);
    const int tid  = threadIdx.x;
    const int lane = tid & 31, wid = tid >> 5;
    const int wm = wid >> 2, wn = wid & 3;
    const int mblk = blockIdx.x * 64, nblk = blockIdx.y * 256;

    float acc[2][8][4];
    #pragma unroll
    for (int i = 0; i < 2; i++)
        #pragma unroll
        for (int j = 0; j < 8; j++)
            #pragma unroll
            for (int q = 0; q < 4; q++) acc[i][j][q] = 0.0f;

    auto issue = [&](int c, int s) {
        const size_t k0 = (size_t)c * 64;
        // B: 256 rows x 64 halves (8 x 16B/thr)
        #pragma unroll
        for (int i = 0; i < 8; i++) {
            int o = tid + i * 256;
            int row = o >> 3, kc = o & 7;
            uint32_t dst = sb + (uint32_t)s * G1_SBST + (uint32_t)row * 128
                         + (uint32_t)((kc ^ (row & 7)) << 4);
            CP_ASYNC16(dst, Xh + (size_t)(nblk + row) * FIN + k0 + kc * 8);
        }
        // A: hi+lo, each 64 rows x 64 halves (2+2 x 16B/thr)
        #pragma unroll
        for (int i = 0; i < 2; i++) {
            int o = tid + i * 256;
            int row = o >> 3, kc = o & 7;
            uint32_t so = (uint32_t)row * 128 + (uint32_t)((kc ^ (row & 7)) << 4);
            uint32_t ab = sb + G1_SA + (uint32_t)s * G1_SAST;
            CP_ASYNC16(ab + so, WTh + (size_t)(mblk + row) * FIN + k0 + kc * 8);
            CP_ASYNC16(ab + 8192 + so, WTl + (size_t)(mblk + row) * FIN + k0 + kc * 8);
        }
    };
    auto compute = [&](int s) {
        const uint32_t baseB = sb + (uint32_t)s * G1_SBST;
        const uint32_t baseA = sb + G1_SA + (uint32_t)s * G1_SAST;
        #pragma unroll
        for (int kk = 0; kk < 4; kk++) {
            uint32_t ah[2][4], al[2][4];
            const int arow = lane & 15;
            const int uA = kk * 2 + (lane >> 4);
            #pragma unroll
            for (int mi = 0; mi < 2; mi++) {
                int r = wm * 32 + mi * 16 + arow;
                uint32_t so = (uint32_t)r * 128 + (uint32_t)((uA ^ (r & 7)) << 4);
                LDSM4(ah[mi], baseA + so);
                LDSM4(al[mi], baseA + 8192 + so);
            }
            #pragma unroll
            for (int g = 0; g < 4; g++) {
                const int nrow = wn * 64 + g * 16 + (lane & 7) + ((lane >> 4) << 3);
                const int uB = kk * 2 + ((lane >> 3) & 1);
                uint32_t bh[4];
                LDSM4(bh, baseB + (uint32_t)nrow * 128 + (uint32_t)((uB ^ (nrow & 7)) << 4));
                #pragma unroll
                for (int mi = 0; mi < 2; mi++)
                    #pragma unroll
                    for (int q = 0; q < 2; q++) {
                        MMA16816(acc[mi][g * 2 + q], ah[mi], &bh[2 * q]);
                        MMA16816(acc[mi][g * 2 + q], al[mi], &bh[2 * q]);
                    }
            }
        }
    };

    issue(0, 0); CP_COMMIT();
    issue(1, 1); CP_COMMIT();
    for (int c = 0; c < NCH1; ++c) {
        if (c + 1 < NCH1) CP_WAIT1(); else CP_WAIT0();
        __syncthreads();
        compute(c & 1);
        __syncthreads();
        if (c + 2 < NCH1) { issue(c + 2, c & 1); CP_COMMIT(); }
    }

    // epilogue: fp16 store to sT[h][n]
    #pragma unroll
    for (int ni = 0; ni < 8; ni++) {
        const int col = nblk + wn * 64 + ni * 8 + (lane & 3) * 2;
        #pragma unroll
        for (int mi = 0; mi < 2; mi++) {
            const int h0 = mblk + wm * 32 + mi * 16 + (lane >> 2);
            const float* c = acc[mi][ni];
            __half2 v0 = __float22half2_rn(make_float2(c[0], c[1]));
            __half2 v1 = __float22half2_rn(make_float2(c[2], c[3]));
            *reinterpret_cast<__half2*>(sT + (size_t)h0 * NROWS + col) = v0;
            *reinterpret_cast<__half2*>(sT + (size_t)(h0 + 8) * NROWS + col) = v1;
        }
    }
}

// ===== GEMM2 + bias + log_softmax fused (unchanged from R6, proven) =====
#define BM2 64
#define BK2 64
#define SBST 32768
#define SA_OFF (3 * SBST)
#define SAST 8192
#define G2_SMEM (SA_OFF + 2 * SAST)
#define NCH2  (NROWS / BK2)

__global__ __launch_bounds__(256, 2)
void gemm2_fused(const float* __restrict__ adj,
                 const __half* __restrict__ Bh,
                 const float* __restrict__ bias,
                 float* __restrict__ embed,
                 float* __restrict__ logp)
{
    extern __shared__ char sm[];
    const uint32_t sb = smem_u32(sm);
    const int tid  = threadIdx.x;
    const int lane = tid & 31, wid = tid >> 5;
    const int wm = wid >> 2, wn = wid & 3;
    const int mblk = blockIdx.x * BM2;

    float acc[2][8][4];
    #pragma unroll
    for (int i = 0; i < 2; i++)
        #pragma unroll
        for (int j = 0; j < 8; j++)
            #pragma unroll
            for (int q = 0; q < 4; q++) acc[i][j][q] = 0.0f;

    auto issueB = [&](int c, int s) {
        const size_t k0 = (size_t)c * BK2;
        #pragma unroll
        for (int i = 0; i < 8; i++) {
            int o = tid + i * 256;
            int row = o >> 3, kc = o & 7;
            uint32_t dst = sb + (uint32_t)s * SBST + (uint32_t)row * 128
                         + (uint32_t)((kc ^ (row & 7)) << 4);
            CP_ASYNC16(dst, Bh + (size_t)row * NROWS + k0 + kc * 8);
        }
    };
    const int arow_ = tid >> 2, aq = tid & 3;
    auto ldgA = [&](int c, float4 av[4]) {
        const float* p = adj + (size_t)(mblk + arow_) * NROWS + (size_t)c * BK2 + aq * 16;
        av[0] = reinterpret_cast<const float4*>(p)[0];
        av[1] = reinterpret_cast<const float4*>(p)[1];
        av[2] = reinterpret_cast<const float4*>(p)[2];
        av[3] = reinterpret_cast<const float4*>(p)[3];
    };
    auto storeA = [&](const float4 av[4], int d) {
        uint32_t w[8];
        #pragma unroll
        for (int i = 0; i < 4; i++) {
            __half2 h0 = __float22half2_rn(make_float2(av[i].x, av[i].y));
            __half2 h1 = __float22half2_rn(make_float2(av[i].z, av[i].w));
            w[2 * i]     = *reinterpret_cast<uint32_t*>(&h0);
            w[2 * i + 1] = *reinterpret_cast<uint32_t*>(&h1);
        }
        uint32_t base = sb + SA_OFF + (uint32_t)d * SAST + (uint32_t)arow_ * 128;
        uint32_t u0 = (uint32_t)((aq * 2) ^ (arow_ & 7)) << 4;
        uint32_t u1 = (uint32_t)((aq * 2 + 1) ^ (arow_ & 7)) << 4;
        asm volatile("st.shared.v4.b32 [%0], {%1,%2,%3,%4};" ::
            "r"(base + u0), "r"(w[0]), "r"(w[1]), "r"(w[2]), "r"(w[3]));
        asm volatile("st.shared.v4.b32 [%0], {%1,%2,%3,%4};" ::
            "r"(base + u1), "r"(w[4]), "r"(w[5]), "r"(w[6]), "r"(w[7]));
    };
    auto compute = [&](int bs, int ad) {
        const uint32_t baseB = sb + (uint32_t)bs * SBST;
        const uint32_t baseA = sb + SA_OFF + (uint32_t)ad * SAST;
        #pragma unroll
        for (int kk = 0; kk < 4; kk++) {
            uint32_t ah[2][4];
            const int arow = lane & 15;
            const int uA = kk * 2 + (lane >> 4);
            #pragma unroll
            for (int mi = 0; mi < 2; mi++) {
                int r = wm * 32 + mi * 16 + arow;
                LDSM4(ah[mi], baseA + (uint32_t)r * 128 + (uint32_t)((uA ^ (r & 7)) << 4));
            }
            #pragma unroll
            for (int g = 0; g < 4; g++) {
                const int nrow = wn * 64 + g * 16 + (lane & 7) + ((lane >> 4) << 3);
                const int uB = kk * 2 + ((lane >> 3) & 1);
                uint32_t bh[4];
                LDSM4(bh, baseB + (uint32_t)nrow * 128 + (uint32_t)((uB ^ (nrow & 7)) << 4));
                #pragma unroll
                for (int mi = 0; mi < 2; mi++)
                    #pragma unroll
                    for (int q = 0; q < 2; q++)
                        MMA16816(acc[mi][g * 2 + q], ah[mi], &bh[2 * q]);
            }
        }
    };

    issueB(0, 0); CP_COMMIT();
    issueB(1, 1); CP_COMMIT();
    float4 av[4];
    ldgA(0, av); storeA(av, 0);
    ldgA(1, av);

    for (int c = 0; c < NCH2; ++c) {
        if (c < NCH2 - 1) CP_WAIT1(); else CP_WAIT0();
        __syncthreads();
        if (c + 1 < NCH2) storeA(av, (c + 1) & 1);
        compute(c % 3, c & 1);
        if (c + 2 < NCH2) { issueB(c + 2, (c + 2) % 3); CP_COMMIT(); }
        if (c + 2 < NCH2) ldgA(c + 2, av);
    }
    __syncthreads();

    #pragma unroll
    for (int ni = 0; ni < 8; ni++) {
        const float2 bv = __ldg(reinterpret_cast<const float2*>(
            bias + wn * 64 + ni * 8 + (lane & 3) * 2));
        #pragma unroll
        for (int mi = 0; mi < 2; mi++) {
            acc[mi][ni][0] += bv.x; acc[mi][ni][1] += bv.y;
            acc[mi][ni][2] += bv.x; acc[mi][ni][3] += bv.y;
        }
    }
    float* part  = reinterpret_cast<float*>(sm);
    float* part2 = reinterpret_cast<float*>(sm + 1024);
    float mx[2][2];
    #pragma unroll
    for (int mi = 0; mi < 2; mi++)
        #pragma unroll
        for (int rh = 0; rh < 2; rh++) {
            float m = -INFINITY;
            #pragma unroll
            for (int ni = 0; ni < 8; ni++)
                m = fmaxf(m, fmaxf(acc[mi][ni][rh * 2], acc[mi][ni][rh * 2 + 1]));
            m = fmaxf(m, __shfl_xor_sync(0xffffffffu, m, 1));
            m = fmaxf(m, __shfl_xor_sync(0xffffffffu, m, 2));
            mx[mi][rh] = m;
        }
    if ((lane & 3) == 0) {
        #pragma unroll
        for (int mi = 0; mi < 2; mi++)
            #pragma unroll
            for (int rh = 0; rh < 2; rh++)
                part[(wm * 32 + mi * 16 + (lane >> 2) + rh * 8) * 4 + wn] = mx[mi][rh];
    }
    __syncthreads();
    float rmax[2][2];
    #pragma unroll
    for (int mi = 0; mi < 2; mi++)
        #pragma unroll
        for (int rh = 0; rh < 2; rh++) {
            int r = wm * 32 + mi * 16 + (lane >> 2) + rh * 8;
            rmax[mi][rh] = fmaxf(fmaxf(part[r * 4], part[r * 4 + 1]),
                                 fmaxf(part[r * 4 + 2], part[r * 4 + 3]));
        }
    float sme[2][2];
    #pragma unroll
    for (int mi = 0; mi < 2; mi++)
        #pragma unroll
        for (int rh = 0; rh < 2; rh++) {
            float s = 0.0f;
            #pragma unroll
            for (int ni = 0; ni < 8; ni++)
                s += __expf(acc[mi][ni][rh * 2] - rmax[mi][rh])
                   + __expf(acc[mi][ni][rh * 2 + 1] - rmax[mi][rh]);
            s += __shfl_xor_sync(0xffffffffu, s, 1);
            s += __shfl_xor_sync(0xffffffffu, s, 2);
            sme[mi][rh] = s;
        }
    if ((lane & 3) == 0) {
        #pragma unroll
        for (int mi = 0; mi < 2; mi++)
            #pragma unroll
            for (int rh = 0; rh < 2; rh++)
                part2[(wm * 32 + mi * 16 + (lane >> 2) + rh * 8) * 4 + wn] = sme[mi][rh];
    }
    __syncthreads();
    float lse[2][2];
    #pragma unroll
    for (int mi = 0; mi < 2; mi++)
        #pragma unroll
        for (int rh = 0; rh < 2; rh++) {
            int r = wm * 32 + mi * 16 + (lane >> 2) + rh * 8;
            lse[mi][rh] = rmax[mi][rh] + __logf(part2[r * 4] + part2[r * 4 + 1]
                                              + part2[r * 4 + 2] + part2[r * 4 + 3]);
        }
    #pragma unroll
    for (int ni = 0; ni < 8; ni++) {
        const int col = wn * 64 + ni * 8 + (lane & 3) * 2;
        #pragma unroll
        for (int mi = 0; mi < 2; mi++) {
            const int r0 = mblk + wm * 32 + mi * 16 + (lane >> 2);
            const float* c = acc[mi][ni];
            *reinterpret_cast<float2*>(embed + (size_t)r0 * FHID + col) =
                make_float2(c[0], c[1]);
            *reinterpret_cast<float2*>(embed + (size_t)(r0 + 8) * FHID + col) =
                make_float2(c[2], c[3]);
            *reinterpret_cast<float2*>(logp + (size_t)r0 * FHID + col) =
                make_float2(c[0] - lse[mi][0], c[1] - lse[mi][0]);
            *reinterpret_cast<float2*>(logp + (size_t)(r0 + 8) * FHID + col) =
                make_float2(c[2] - lse[mi][1], c[3] - lse[mi][1]);
        }
    }
}

// ================= launch =================
extern "C" void kernel_launch(void* const* d_in, const int* in_sizes, int n_in,
                              void* d_out, int out_size)
{
    const float* x   = (const float*)d_in[0];
    const float* adj = (const float*)d_in[1];
    const float* W   = (const float*)d_in[2];
    const float* b   = (const float*)d_in[3];
    float* out = (float*)d_out;

    float* embed;
    __half *xh, *WTh, *WTl, *sT;
    cudaGetSymbolAddress((void**)&xh,  g_xh);
    cudaGetSymbolAddress((void**)&WTh, g_WTh);
    cudaGetSymbolAddress((void**)&WTl, g_WTl);
    cudaGetSymbolAddress((void**)&sT,  g_sT);

    float* logp = out;
    if (out_size >= 2 * NROWS * FHID) embed = out + (size_t)NROWS * FHID;
    else cudaGetSymbolAddress((void**)&embed, g_embed_fallback);

    cudaFuncSetAttribute(gemm1_hmma, cudaFuncAttributeMaxDynamicSharedMemorySize, G1_SMEM);
    cudaFuncSetAttribute(gemm2_fused, cudaFuncAttributeMaxDynamicSharedMemorySize, G2_SMEM);

    // prep: WT hi/lo, x -> fp16
    wt_split<<<dim3(FIN / 32, FHID / 32), 256>>>(W, WTh, WTl);
    x_half<<<(NROWS * FIN) / 1024, 256>>>(x, xh);
    // GEMM1 (HMMA): sT = WT @ xT, fp16 out, already transposed
    gemm1_hmma<<<dim3(FHID / 64, NROWS / 256), 256, G1_SMEM>>>(WTh, WTl, xh, sT);
    // GEMM2 + bias + log_softmax fused
    gemm2_fused<<<NROWS / BM2, 256, G2_SMEM>>>(adj, sT, b, embed, logp);
}